// round 6
// baseline (speedup 1.0000x reference)
#include <cuda_runtime.h>
#include <cuda_fp16.h>
#include <cstdint>

// Problem constants
#define VOCAB 8192
#define HID   256
#define BATCH 32
#define SEQ   256
#define G3H   768   // 3*HID

// ---------------------------------------------------------------------------
// Scratch (static device globals; allocation inside kernel_launch is banned)
// ---------------------------------------------------------------------------
__device__ float  g_WT[(size_t)VOCAB * G3H];       // W_ih^T with b_ih folded: [V][768]
__device__ __half g_Y [(size_t)SEQ * BATCH * HID]; // GRU outputs, fp16, row m = t*B+b
__device__ __half g_Wd[(size_t)VOCAB * HID];       // W_dense in fp16

// ---------------------------------------------------------------------------
// PTX helpers — base-family features only (plain sm_103 target: no tcgen05).
// ---------------------------------------------------------------------------
__device__ __forceinline__ uint32_t smem_to_u32(const void* p) {
    uint32_t a;
    asm("{ .reg .u64 t; cvta.to.shared.u64 t, %1; cvt.u32.u64 %0, t; }" : "=r"(a) : "l"(p));
    return a;
}
__device__ __forceinline__ uint32_t cluster_rank() {
    uint32_t r; asm("mov.u32 %0, %%cluster_ctarank;" : "=r"(r)); return r;
}

#define CLUSTER_ARRIVE() asm volatile("barrier.cluster.arrive.aligned;" ::: "memory")
#define CLUSTER_WAIT()   asm volatile("barrier.cluster.wait.aligned;"   ::: "memory")

#define STS_CLUSTER_F32(addr, rank, val) \
    asm volatile("{\n\t.reg .b32 ra;\n\t" \
                 "mapa.shared::cluster.u32 ra, %0, %1;\n\t" \
                 "st.shared::cluster.f32 [ra], %2;\n\t}" \
                 :: "r"(addr), "r"(rank), "f"(val) : "memory")

#define FMA2(d, a, b, cc) \
    asm("fma.rn.f32x2 %0, %1, %2, %3;" : "=l"(d) : "l"(a), "l"(b), "l"(cc))

__device__ __forceinline__ unsigned long long pack_f32x2(float lo, float hi) {
    unsigned long long r;
    asm("mov.b64 %0, {%1, %2};" : "=l"(r) : "f"(lo), "f"(hi));
    return r;
}
__device__ __forceinline__ void unpack_f32x2(unsigned long long v, float& lo, float& hi) {
    asm("mov.b64 {%0, %1}, %2;" : "=f"(lo), "=f"(hi) : "l"(v));
}

// mma.sync m16n8k16 fp16 x fp16 -> fp32 (sm_80-base)
#define MMA_16816(c, a, b) \
    asm volatile("mma.sync.aligned.m16n8k16.row.col.f32.f16.f16.f32 " \
                 "{%0,%1,%2,%3}, {%4,%5,%6,%7}, {%8,%9}, {%0,%1,%2,%3};" \
                 : "+f"((c)[0]), "+f"((c)[1]), "+f"((c)[2]), "+f"((c)[3]) \
                 : "r"((a)[0]), "r"((a)[1]), "r"((a)[2]), "r"((a)[3]), \
                   "r"((b)[0]), "r"((b)[1]))

#define LDMATRIX_X4(r, addr) \
    asm volatile("ldmatrix.sync.aligned.m8n8.x4.shared.b16 {%0,%1,%2,%3}, [%4];" \
                 : "=r"((r)[0]), "=r"((r)[1]), "=r"((r)[2]), "=r"((r)[3]) \
                 : "r"(addr))

#define CP_ASYNC16(dst_u32, src_ptr) \
    asm volatile("cp.async.cg.shared.global [%0], [%1], 16;" \
                 :: "r"(dst_u32), "l"(src_ptr))
#define CP_ASYNC_COMMIT() asm volatile("cp.async.commit_group;" ::: "memory")

// ---------------------------------------------------------------------------
// Kernel 1: WT[v][j] = W_ih[j][v] + b_ih[j]   (tiled transpose, fused bias)
// ---------------------------------------------------------------------------
__global__ void transpose_wih_kernel(const float* __restrict__ W_ih,
                                     const float* __restrict__ b_ih) {
    __shared__ float tile[32][33];
    const int v0 = blockIdx.x * 32;
    const int j0 = blockIdx.y * 32;
    const int tx = threadIdx.x, ty = threadIdx.y;
    #pragma unroll
    for (int i = 0; i < 32; i += 8) {
        int j = j0 + ty + i;
        tile[ty + i][tx] = W_ih[(size_t)j * VOCAB + v0 + tx];
    }
    __syncthreads();
    #pragma unroll
    for (int i = 0; i < 32; i += 8) {
        int v = v0 + ty + i;
        int j = j0 + tx;
        g_WT[(size_t)v * G3H + j] = tile[tx][ty + i] + b_ih[j];
    }
}

// ---------------------------------------------------------------------------
// Kernel 2: W_dense fp32 -> fp16
// ---------------------------------------------------------------------------
__global__ void convert_wd_kernel(const float* __restrict__ W_dense) {
    int i = blockIdx.x * blockDim.x + threadIdx.x;
    if (i < VOCAB * HID) g_Wd[i] = __float2half(W_dense[i]);
}

// ---------------------------------------------------------------------------
// Kernel 3: GRU recurrence. 16 clusters x 4 CTAs; each cluster runs TWO
// batches (A, B) interleaved so every cluster-barrier wait is separated from
// its arrive by a full batch-step of work (barrier latency fully hidden).
// W_hh register slice (64 x f32x2) is shared by both batches.
// Phase stream per iter t:
//   A(t); [t>0] wait(B-stores t-1); arrive(A-stores t);
//   B(t);       wait(A-stores t);   arrive(B-stores t);
// + one final wait after the loop. Strict arrive/wait alternation; every
// wait doubles as a CTA-wide sync (all threads block in .aligned wait).
// ---------------------------------------------------------------------------
__global__ void __launch_bounds__(384, 1) __cluster_dims__(4, 1, 1)
gru_kernel(const int* __restrict__ X, const float* __restrict__ state,
           const float* __restrict__ W_hh, const float* __restrict__ b_hh,
           float* __restrict__ out_state) {
    __shared__ __align__(16) float hbuf[2][2][256];   // [batch][pingpong][slot]
    __shared__ float ghsA[192], ghsB[192];
    __shared__ int sX[2][SEQ];

    const int tid = threadIdx.x;
    const int c = (int)cluster_rank();
    const int g = blockIdx.x >> 2;
    const int bA = 2 * g, bB = 2 * g + 1;

    const int half = tid & 1;                 // K half (adjacent lanes)
    const int out_local = tid >> 1;           // 0..191
    const int row = (out_local >> 6) * 256 + c * 64 + (out_local & 63);
    const int slot = c * 64 + (tid & 63);     // valid for tid<64 use

    // Register-resident W_hh slice: 128 floats as 64 packed f32x2 (shared A/B)
    unsigned long long w2[64];
    {
        const float4* wrow = (const float4*)(W_hh + (size_t)row * HID + half * 128);
        #pragma unroll
        for (int i = 0; i < 32; i++) {
            float4 v = wrow[i];
            w2[2 * i]     = pack_f32x2(v.x, v.y);
            w2[2 * i + 1] = pack_f32x2(v.z, v.w);
        }
    }
    const float bhh = b_hh[row];

    if (tid < 256) {
        hbuf[0][0][tid] = state[bA * HID + tid];
        hbuf[1][0][tid] = state[bB * HID + tid];
    }
    for (int i = tid; i < SEQ; i += 384) {
        sX[0][i] = X[bA * SEQ + i];
        sX[1][i] = X[bB * SEQ + i];
    }
    __syncthreads();

    // gx prefetch for t=0, both batches
    float xrA = 0.f, xzA = 0.f, xnA = 0.f, xrB = 0.f, xzB = 0.f, xnB = 0.f;
    if (tid < 64) {
        const float* ga = g_WT + (size_t)sX[0][0] * G3H + c * 64 + tid;
        xrA = ga[0]; xzA = ga[256]; xnA = ga[512];
        const float* gb = g_WT + (size_t)sX[1][0] * G3H + c * 64 + tid;
        xrB = gb[0]; xzB = gb[256]; xnB = gb[512];
    }

    const uint32_t hbuf_u32 = smem_to_u32(hbuf);

    for (int t = 0; t < SEQ; t++) {
        const int p = t & 1;

        // ================= batch A =================
        {
            unsigned long long acc0 = 0ull, acc1 = 0ull;
            const ulonglong2* h2 = (const ulonglong2*)(&hbuf[0][p][half * 128]);
            #pragma unroll
            for (int i = 0; i < 32; i++) {
                ulonglong2 hv = h2[i];
                FMA2(acc0, w2[2 * i],     hv.x, acc0);
                FMA2(acc1, w2[2 * i + 1], hv.y, acc1);
            }
            float l0, h0, l1, h1;
            unpack_f32x2(acc0, l0, h0);
            unpack_f32x2(acc1, l1, h1);
            float acc = (l0 + h0) + (l1 + h1);
            acc += __shfl_xor_sync(0xffffffffu, acc, 1);
            if (!half) ghsA[out_local] = acc + bhh;
        }
        __syncthreads();

        float hnewA = 0.f;
        if (tid < 64) {
            const float hr = ghsA[tid], hz = ghsA[64 + tid], hn = ghsA[128 + tid];
            const float r = __fdividef(1.f, 1.f + __expf(-(xrA + hr)));
            const float z = __fdividef(1.f, 1.f + __expf(-(xzA + hz)));
            const float y = xnA + r * hn;
            const float n = 1.f - __fdividef(2.f, __expf(2.f * y) + 1.f);
            const float hp = hbuf[0][p][slot];
            hnewA = n + z * (hp - n);
            hbuf[0][p ^ 1][slot] = hnewA;
            const uint32_t a = hbuf_u32 + (uint32_t)((((p ^ 1) * 256) + slot) * 4);
            #pragma unroll
            for (int r2 = 0; r2 < 4; r2++)
                if (r2 != c) STS_CLUSTER_F32(a, r2, hnewA);
        }

        if (t > 0) CLUSTER_WAIT();       // B-stores(t-1): hB[t] ready everywhere
        CLUSTER_ARRIVE();                // signal A-stores(t)

        if (tid < 64) {                  // hidden under A-barrier propagation
            g_Y[((size_t)(t * BATCH + bA)) * HID + slot] = __float2half(hnewA);
            if (t == SEQ - 1) {
                out_state[bA * HID + slot] = hnewA;
            } else {
                const float* ga = g_WT + (size_t)sX[0][t + 1] * G3H + c * 64 + tid;
                xrA = ga[0]; xzA = ga[256]; xnA = ga[512];
            }
        }

        // ================= batch B =================
        {
            unsigned long long acc0 = 0ull, acc1 = 0ull;
            const ulonglong2* h2 = (const ulonglong2*)(&hbuf[1][p][half * 128]);
            #pragma unroll
            for (int i = 0; i < 32; i++) {
                ulonglong2 hv = h2[i];
                FMA2(acc0, w2[2 * i],     hv.x, acc0);
                FMA2(acc1, w2[2 * i + 1], hv.y, acc1);
            }
            float l0, h0, l1, h1;
            unpack_f32x2(acc0, l0, h0);
            unpack_f32x2(acc1, l1, h1);
            float acc = (l0 + h0) + (l1 + h1);
            acc += __shfl_xor_sync(0xffffffffu, acc, 1);
            if (!half) ghsB[out_local] = acc + bhh;
        }
        __syncthreads();

        float hnewB = 0.f;
        if (tid < 64) {
            const float hr = ghsB[tid], hz = ghsB[64 + tid], hn = ghsB[128 + tid];
            const float r = __fdividef(1.f, 1.f + __expf(-(xrB + hr)));
            const float z = __fdividef(1.f, 1.f + __expf(-(xzB + hz)));
            const float y = xnB + r * hn;
            const float n = 1.f - __fdividef(2.f, __expf(2.f * y) + 1.f);
            const float hp = hbuf[1][p][slot];
            hnewB = n + z * (hp - n);
            hbuf[1][p ^ 1][slot] = hnewB;
            const uint32_t a = hbuf_u32 + (uint32_t)((512 + ((p ^ 1) * 256) + slot) * 4);
            #pragma unroll
            for (int r2 = 0; r2 < 4; r2++)
                if (r2 != c) STS_CLUSTER_F32(a, r2, hnewB);
        }

        CLUSTER_WAIT();                  // A-stores(t): hA[t+1] ready everywhere
        CLUSTER_ARRIVE();                // signal B-stores(t)

        if (tid < 64) {                  // hidden under B-barrier propagation
            g_Y[((size_t)(t * BATCH + bB)) * HID + slot] = __float2half(hnewB);
            if (t == SEQ - 1) {
                out_state[bB * HID + slot] = hnewB;
            } else {
                const float* gb = g_WT + (size_t)sX[1][t + 1] * G3H + c * 64 + tid;
                xrB = gb[0]; xzB = gb[256]; xnB = gb[512];
            }
        }
    }
    CLUSTER_WAIT();   // pairs with final arrive; peers' stores landed
}

// ---------------------------------------------------------------------------
// Kernel 4: dense output GEMM via mma.sync (HMMA), fp16 in / fp32 accumulate.
// CTA 128x128, 4 warps of 64x64. BK=32 cp.async double-buffer with ONE
// __syncthreads per K-iter (fill(next) issued after the sync) and all LDSM
// fragments for both kk-steps front-loaded before the 64 MMAs.
// ---------------------------------------------------------------------------
__global__ void __launch_bounds__(128, 2)
dense_kernel(const float* __restrict__ b_dense, float* __restrict__ out) {
    __shared__ __half sA[2][128][40];   // 32 halves + 8 pad: conflict-free LDSM
    __shared__ __half sB[2][128][40];
    __shared__ float sbias[128];

    const int tid = threadIdx.x;
    const int wid = tid >> 5;
    const int lane = tid & 31;
    const int n0 = blockIdx.x * 128;
    const int m0 = blockIdx.y * 128;
    const int wm = wid >> 1;     // 0..1 -> rows wm*64
    const int wn = wid & 1;      // 0..1 -> cols wn*64

    float c[4][8][4] = {};

    sbias[tid] = b_dense[n0 + tid];

    auto fill = [&](int kb, int buf) {
        const int ko = kb * 32;
        #pragma unroll
        for (int i = 0; i < 4; i++) {
            const int chunk = i * 128 + tid;       // 0..511 (16B chunks)
            const int r = chunk >> 2;
            const int g = (chunk & 3) * 8;
            CP_ASYNC16(smem_to_u32(&sA[buf][r][g]),
                       (const void*)(g_Y + (size_t)(m0 + r) * HID + ko + g));
            CP_ASYNC16(smem_to_u32(&sB[buf][r][g]),
                       (const void*)(g_Wd + (size_t)(n0 + r) * HID + ko + g));
        }
        CP_ASYNC_COMMIT();
    };

    fill(0, 0);
    #pragma unroll
    for (int kb = 0; kb < 8; kb++) {
        const int buf = kb & 1;
        asm volatile("cp.async.wait_group 0;" ::: "memory");
        __syncthreads();                  // buf ready; all done reading buf^1
        if (kb < 7) fill(kb + 1, buf ^ 1);

        // Front-load all fragments for kk=0 and kk=16
        uint32_t a[2][4][4];
        uint32_t bfr[2][8][2];
        #pragma unroll
        for (int s = 0; s < 2; s++) {
            const int kk = s * 16;
            #pragma unroll
            for (int mt = 0; mt < 4; mt++) {
                uint32_t addr = smem_to_u32(
                    &sA[buf][wm * 64 + mt * 16 + (lane & 15)][(lane >> 4) * 8 + kk]);
                LDMATRIX_X4(a[s][mt], addr);
            }
            #pragma unroll
            for (int nt2 = 0; nt2 < 4; nt2++) {
                uint32_t r4[4];
                uint32_t addr = smem_to_u32(
                    &sB[buf][wn * 64 + nt2 * 16 + ((lane >> 4) << 3) + (lane & 7)]
                            [((lane >> 3) & 1) * 8 + kk]);
                LDMATRIX_X4(r4, addr);
                bfr[s][2 * nt2][0] = r4[0];     bfr[s][2 * nt2][1] = r4[1];
                bfr[s][2 * nt2 + 1][0] = r4[2]; bfr[s][2 * nt2 + 1][1] = r4[3];
            }
        }
        #pragma unroll
        for (int s = 0; s < 2; s++)
            #pragma unroll
            for (int mt = 0; mt < 4; mt++)
                #pragma unroll
                for (int nt = 0; nt < 8; nt++)
                    MMA_16816(c[mt][nt], a[s][mt], bfr[s][nt]);
    }

    // Epilogue: +bias, v2 stores (fragment: row=lane/4(+8), col=(lane%4)*2)
    const int er = lane >> 2;
    const int ec = (lane & 3) * 2;
    #pragma unroll
    for (int mt = 0; mt < 4; mt++) {
        const size_t row0 = (size_t)(m0 + wm * 64 + mt * 16 + er);
        #pragma unroll
        for (int nt = 0; nt < 8; nt++) {
            const int cl = wn * 64 + nt * 8 + ec;
            const float b0 = sbias[cl], b1 = sbias[cl + 1];
            float2 v0 = make_float2(c[mt][nt][0] + b0, c[mt][nt][1] + b1);
            float2 v1 = make_float2(c[mt][nt][2] + b0, c[mt][nt][3] + b1);
            *(float2*)&out[row0 * VOCAB + n0 + cl] = v0;
            *(float2*)&out[(row0 + 8) * VOCAB + n0 + cl] = v1;
        }
    }
}

// ---------------------------------------------------------------------------
// kernel_launch — graph-capturable, allocation-free
// Inputs: X(i32), state, W_ih, W_hh, b_ih, b_hh, W_dense, b_dense
// Output: [8192*8192 fp32 logits][32*256 fp32 final state]
// ---------------------------------------------------------------------------
extern "C" void kernel_launch(void* const* d_in, const int* in_sizes, int n_in,
                              void* d_out, int out_size) {
    const int*   X       = (const int*)  d_in[0];
    const float* state   = (const float*)d_in[1];
    const float* W_ih    = (const float*)d_in[2];
    const float* W_hh    = (const float*)d_in[3];
    const float* b_ih    = (const float*)d_in[4];
    const float* b_hh    = (const float*)d_in[5];
    const float* W_dense = (const float*)d_in[6];
    const float* b_dense = (const float*)d_in[7];
    float* out = (float*)d_out;
    float* out_state = out + (size_t)SEQ * BATCH * VOCAB;

    transpose_wih_kernel<<<dim3(VOCAB / 32, G3H / 32), dim3(32, 8)>>>(W_ih, b_ih);
    convert_wd_kernel<<<(VOCAB * HID + 1023) / 1024, 1024>>>(W_dense);
    gru_kernel<<<(BATCH / 2) * 4, 384>>>(X, state, W_hh, b_hh, out_state);
    dense_kernel<<<dim3(VOCAB / 128, SEQ * BATCH / 128), 128>>>(b_dense, out);
}

// round 7
// speedup vs baseline: 1.0118x; 1.0118x over previous
#include <cuda_runtime.h>
#include <cuda_fp16.h>
#include <cstdint>

// Problem constants
#define VOCAB 8192
#define HID   256
#define BATCH 32
#define SEQ   256
#define G3H   768   // 3*HID

// ---------------------------------------------------------------------------
// Scratch (static device globals; allocation inside kernel_launch is banned)
// ---------------------------------------------------------------------------
__device__ float  g_WT[(size_t)VOCAB * G3H];       // W_ih^T with b_ih folded: [V][768]
__device__ __half g_Y [(size_t)SEQ * BATCH * HID]; // GRU outputs, fp16, row m = t*B+b
__device__ __half g_Wd[(size_t)VOCAB * HID];       // W_dense in fp16

// ---------------------------------------------------------------------------
// PTX helpers — base-family features only (plain sm_103 target: no tcgen05).
// ---------------------------------------------------------------------------
__device__ __forceinline__ uint32_t smem_to_u32(const void* p) {
    uint32_t a;
    asm("{ .reg .u64 t; cvta.to.shared.u64 t, %1; cvt.u32.u64 %0, t; }" : "=r"(a) : "l"(p));
    return a;
}
__device__ __forceinline__ uint32_t cluster_rank() {
    uint32_t r; asm("mov.u32 %0, %%cluster_ctarank;" : "=r"(r)); return r;
}

#define CLUSTER_ARRIVE() asm volatile("barrier.cluster.arrive.aligned;" ::: "memory")
#define CLUSTER_WAIT()   asm volatile("barrier.cluster.wait.aligned;"   ::: "memory")

#define STS_CLUSTER_F32(addr, rank, val) \
    asm volatile("{\n\t.reg .b32 ra;\n\t" \
                 "mapa.shared::cluster.u32 ra, %0, %1;\n\t" \
                 "st.shared::cluster.f32 [ra], %2;\n\t}" \
                 :: "r"(addr), "r"(rank), "f"(val) : "memory")

#define MBARRIER_INIT(mbar_smem_addr, count) \
    asm volatile("mbarrier.init.shared.b64 [%0], %1;" \
        :: "r"((uint32_t)(mbar_smem_addr)), "r"((uint32_t)(count)) : "memory")

// Arrive (release, cluster scope) on the mbarrier at the same smem offset in
// cluster CTA `rank` (rank may be own rank).
#define MBAR_ARRIVE_REL_CLUSTER(mbar_smem_addr, rank) \
    asm volatile("{\n\t.reg .b32 ra;\n\t" \
                 "mapa.shared::cluster.u32 ra, %0, %1;\n\t" \
                 "mbarrier.arrive.release.cluster.shared::cluster.b64 _, [ra];\n\t}" \
                 :: "r"((uint32_t)(mbar_smem_addr)), "r"((uint32_t)(rank)) : "memory")

// Wait (acquire, cluster scope) on local mbarrier for given phase parity.
#define MBAR_WAIT_PARITY_CLUSTER(mbar_smem_addr, phase_parity) do { \
    uint32_t _mbar = (uint32_t)(mbar_smem_addr); \
    uint32_t _par = (uint32_t)(phase_parity); \
    uint32_t _done; \
    asm volatile("{\n\t.reg .pred p;\n\t" \
        "mbarrier.try_wait.parity.acquire.cluster.shared::cta.b64 p, [%1], %2;\n\t" \
        "selp.b32 %0, 1, 0, p;\n\t}" : "=r"(_done) : "r"(_mbar), "r"(_par) : "memory"); \
    if (!_done) { \
        asm volatile("{\n\t.reg .pred P1;\n\t" \
            "WAIT_LOOP_%=:\n\t" \
            "mbarrier.try_wait.parity.acquire.cluster.shared::cta.b64 P1, [%0], %1, 0x989680;\n\t" \
            "@P1 bra.uni WAIT_DONE_%=;\n\t" \
            "bra.uni WAIT_LOOP_%=;\n\t" \
            "WAIT_DONE_%=:\n\t}" :: "r"(_mbar), "r"(_par) : "memory"); \
    } \
} while (0)

#define FENCE_ACQREL_CLUSTER() asm volatile("fence.acq_rel.cluster;" ::: "memory")

#define FMA2(d, a, b, cc) \
    asm("fma.rn.f32x2 %0, %1, %2, %3;" : "=l"(d) : "l"(a), "l"(b), "l"(cc))

__device__ __forceinline__ unsigned long long pack_f32x2(float lo, float hi) {
    unsigned long long r;
    asm("mov.b64 %0, {%1, %2};" : "=l"(r) : "f"(lo), "f"(hi));
    return r;
}
__device__ __forceinline__ void unpack_f32x2(unsigned long long v, float& lo, float& hi) {
    asm("mov.b64 {%0, %1}, %2;" : "=f"(lo), "=f"(hi) : "l"(v));
}

// mma.sync m16n8k16 fp16 x fp16 -> fp32 (sm_80-base)
#define MMA_16816(c, a, b) \
    asm volatile("mma.sync.aligned.m16n8k16.row.col.f32.f16.f16.f32 " \
                 "{%0,%1,%2,%3}, {%4,%5,%6,%7}, {%8,%9}, {%0,%1,%2,%3};" \
                 : "+f"((c)[0]), "+f"((c)[1]), "+f"((c)[2]), "+f"((c)[3]) \
                 : "r"((a)[0]), "r"((a)[1]), "r"((a)[2]), "r"((a)[3]), \
                   "r"((b)[0]), "r"((b)[1]))

#define LDMATRIX_X4(r, addr) \
    asm volatile("ldmatrix.sync.aligned.m8n8.x4.shared.b16 {%0,%1,%2,%3}, [%4];" \
                 : "=r"((r)[0]), "=r"((r)[1]), "=r"((r)[2]), "=r"((r)[3]) \
                 : "r"(addr))

#define CP_ASYNC16(dst_u32, src_ptr) \
    asm volatile("cp.async.cg.shared.global [%0], [%1], 16;" \
                 :: "r"(dst_u32), "l"(src_ptr))
#define CP_ASYNC_COMMIT() asm volatile("cp.async.commit_group;" ::: "memory")

// ---------------------------------------------------------------------------
// Kernel 1: WT[v][j] = W_ih[j][v] + b_ih[j]   (tiled transpose, fused bias)
// ---------------------------------------------------------------------------
__global__ void transpose_wih_kernel(const float* __restrict__ W_ih,
                                     const float* __restrict__ b_ih) {
    __shared__ float tile[32][33];
    const int v0 = blockIdx.x * 32;
    const int j0 = blockIdx.y * 32;
    const int tx = threadIdx.x, ty = threadIdx.y;
    #pragma unroll
    for (int i = 0; i < 32; i += 8) {
        int j = j0 + ty + i;
        tile[ty + i][tx] = W_ih[(size_t)j * VOCAB + v0 + tx];
    }
    __syncthreads();
    #pragma unroll
    for (int i = 0; i < 32; i += 8) {
        int v = v0 + ty + i;
        int j = j0 + tx;
        g_WT[(size_t)v * G3H + j] = tile[tx][ty + i] + b_ih[j];
    }
}

// ---------------------------------------------------------------------------
// Kernel 2: W_dense fp32 -> fp16
// ---------------------------------------------------------------------------
__global__ void convert_wd_kernel(const float* __restrict__ W_dense) {
    int i = blockIdx.x * blockDim.x + threadIdx.x;
    if (i < VOCAB * HID) g_Wd[i] = __float2half(W_dense[i]);
}

// ---------------------------------------------------------------------------
// Kernel 3: GRU recurrence. 32 clusters (one per batch) x 4 CTAs.
// R5 structure, but the per-step cluster barrier is replaced by 2 ping-pong
// mbarriers per CTA (count=4: one elected arrive from each cluster CTA).
// Arrives at end of step t target mbar[(t+1)&1]; step s>=1 waits mbar[s&1]
// at parity ((s-1)>>1)&1. mbarrier wakeup (~60-90cyc) vs UCGABAR_WAIT (~490).
// ---------------------------------------------------------------------------
__global__ void __launch_bounds__(384, 1) __cluster_dims__(4, 1, 1)
gru_kernel(const int* __restrict__ X, const float* __restrict__ state,
           const float* __restrict__ W_hh, const float* __restrict__ b_hh,
           float* __restrict__ out_state) {
    __shared__ __align__(16) float hbuf[2][256];
    __shared__ float ghs[192];
    __shared__ int sX[SEQ];
    __shared__ __align__(8) unsigned long long mbar[2];

    const int tid = threadIdx.x;
    const int c = (int)cluster_rank();
    const int b = blockIdx.x >> 2;

    const int half = tid & 1;                 // K half (adjacent lanes)
    const int out_local = tid >> 1;           // 0..191
    const int row = (out_local >> 6) * 256 + c * 64 + (out_local & 63);
    const int slot = c * 64 + (tid & 63);     // valid for tid<64 use

    // Register-resident W_hh slice: 128 floats as 64 packed f32x2
    unsigned long long w2[64];
    {
        const float4* wrow = (const float4*)(W_hh + (size_t)row * HID + half * 128);
        #pragma unroll
        for (int i = 0; i < 32; i++) {
            float4 v = wrow[i];
            w2[2 * i]     = pack_f32x2(v.x, v.y);
            w2[2 * i + 1] = pack_f32x2(v.z, v.w);
        }
    }
    const float bhh = b_hh[row];

    if (tid < 256) hbuf[0][tid] = state[b * HID + tid];
    for (int i = tid; i < SEQ; i += 384) sX[i] = X[b * SEQ + i];
    const uint32_t mbar_u32[2] = { smem_to_u32(&mbar[0]), smem_to_u32(&mbar[1]) };
    if (tid == 0) {
        MBARRIER_INIT(mbar_u32[0], 4);
        MBARRIER_INIT(mbar_u32[1], 4);
    }
    __syncthreads();
    // All CTAs' mbarriers initialized before any remote arrive can land.
    CLUSTER_ARRIVE(); CLUSTER_WAIT();

    // gx prefetch for t=0
    float xr = 0.f, xz = 0.f, xn = 0.f;
    if (tid < 64) {
        const float* gxp = g_WT + (size_t)sX[0] * G3H + c * 64 + tid;
        xr = gxp[0]; xz = gxp[256]; xn = gxp[512];
    }

    const uint32_t hbuf_u32 = smem_to_u32(hbuf);

    for (int t = 0; t < SEQ; t++) {
        const int p = t & 1;
        if (t > 0)
            MBAR_WAIT_PARITY_CLUSTER(mbar_u32[t & 1], ((t - 1) >> 1) & 1);

        // dot(W_row[half], h[half]) with packed f32x2, 2 indep chains
        unsigned long long acc0 = 0ull, acc1 = 0ull;
        const ulonglong2* h2 = (const ulonglong2*)(&hbuf[p][half * 128]);
        #pragma unroll
        for (int i = 0; i < 32; i++) {
            ulonglong2 hv = h2[i];
            FMA2(acc0, w2[2 * i],     hv.x, acc0);
            FMA2(acc1, w2[2 * i + 1], hv.y, acc1);
        }
        float l0, h0, l1, h1;
        unpack_f32x2(acc0, l0, h0);
        unpack_f32x2(acc1, l1, h1);
        float acc = (l0 + h0) + (l1 + h1);
        acc += __shfl_xor_sync(0xffffffffu, acc, 1);   // combine K halves
        if (!half) ghs[out_local] = acc + bhh;
        __syncthreads();

        float hnew = 0.f;
        if (tid < 64) {
            const float hr = ghs[tid], hz = ghs[64 + tid], hn = ghs[128 + tid];
            const float r = __fdividef(1.f, 1.f + __expf(-(xr + hr)));
            const float z = __fdividef(1.f, 1.f + __expf(-(xz + hz)));
            const float y = xn + r * hn;
            const float n = 1.f - __fdividef(2.f, __expf(2.f * y) + 1.f);
            const float hp = hbuf[p][slot];
            hnew = n + z * (hp - n);                    // (1-z)*n + z*h

            hbuf[p ^ 1][slot] = hnew;                   // local
            const uint32_t a = hbuf_u32 + (uint32_t)((((p ^ 1) * 256) + slot) * 4);
            #pragma unroll
            for (int r2 = 0; r2 < 4; r2++)
                if (r2 != c) STS_CLUSTER_F32(a, r2, hnew);
            FENCE_ACQREL_CLUSTER();                     // publish remote stores
        }
        __syncthreads();       // all gate stores ordered before the arrives

        if (tid == 0) {
            const uint32_t mnext = mbar_u32[(t + 1) & 1];
            #pragma unroll
            for (int r2 = 0; r2 < 4; r2++)
                MBAR_ARRIVE_REL_CLUSTER(mnext, r2);
        }

        // Posted work while arrives/stores propagate
        if (tid < 64) {
            g_Y[((size_t)(t * BATCH + b)) * HID + slot] = __float2half(hnew);
            if (t == SEQ - 1) {
                out_state[b * HID + slot] = hnew;
            } else {
                const float* gxp = g_WT + (size_t)sX[t + 1] * G3H + c * 64 + tid;
                xr = gxp[0]; xz = gxp[256]; xn = gxp[512];
            }
        }
    }
    // Keep all smem alive until every CTA's final remote stores landed.
    CLUSTER_ARRIVE(); CLUSTER_WAIT();
}

// ---------------------------------------------------------------------------
// Kernel 4: dense output GEMM via mma.sync (HMMA), fp16 in / fp32 accumulate.
// CTA 128x128, 4 warps of 64x64. BK=32 cp.async double-buffer, fragments
// front-loaded. NEW: 8x8 supertile swizzle of block IDs so concurrent CTAs
// share A/B row-blocks in L2 (cuts L2 read traffic ~8x; L2 was 57%).
// ---------------------------------------------------------------------------
__global__ void __launch_bounds__(128, 2)
dense_kernel(const float* __restrict__ b_dense, float* __restrict__ out) {
    __shared__ __half sA[2][128][40];
    __shared__ __half sB[2][128][40];
    __shared__ float sbias[128];

    const int tid = threadIdx.x;
    const int wid = tid >> 5;
    const int lane = tid & 31;

    // 8x8 supertile swizzle over the 64x64 tile grid
    const int bid = blockIdx.y * gridDim.x + blockIdx.x;
    const int st = bid >> 6;              // supertile id (0..63)
    const int within = bid & 63;
    const int n_tile = (st & 7) * 8 + (within & 7);
    const int m_tile = (st >> 3) * 8 + (within >> 3);
    const int n0 = n_tile * 128;
    const int m0 = m_tile * 128;

    const int wm = wid >> 1;     // 0..1 -> rows wm*64
    const int wn = wid & 1;      // 0..1 -> cols wn*64

    float c[4][8][4] = {};

    sbias[tid] = b_dense[n0 + tid];

    auto fill = [&](int kb, int buf) {
        const int ko = kb * 32;
        #pragma unroll
        for (int i = 0; i < 4; i++) {
            const int chunk = i * 128 + tid;       // 0..511 (16B chunks)
            const int r = chunk >> 2;
            const int g = (chunk & 3) * 8;
            CP_ASYNC16(smem_to_u32(&sA[buf][r][g]),
                       (const void*)(g_Y + (size_t)(m0 + r) * HID + ko + g));
            CP_ASYNC16(smem_to_u32(&sB[buf][r][g]),
                       (const void*)(g_Wd + (size_t)(n0 + r) * HID + ko + g));
        }
        CP_ASYNC_COMMIT();
    };

    fill(0, 0);
    #pragma unroll
    for (int kb = 0; kb < 8; kb++) {
        const int buf = kb & 1;
        asm volatile("cp.async.wait_group 0;" ::: "memory");
        __syncthreads();
        if (kb < 7) fill(kb + 1, buf ^ 1);

        uint32_t a[2][4][4];
        uint32_t bfr[2][8][2];
        #pragma unroll
        for (int s = 0; s < 2; s++) {
            const int kk = s * 16;
            #pragma unroll
            for (int mt = 0; mt < 4; mt++) {
                uint32_t addr = smem_to_u32(
                    &sA[buf][wm * 64 + mt * 16 + (lane & 15)][(lane >> 4) * 8 + kk]);
                LDMATRIX_X4(a[s][mt], addr);
            }
            #pragma unroll
            for (int nt2 = 0; nt2 < 4; nt2++) {
                uint32_t r4[4];
                uint32_t addr = smem_to_u32(
                    &sB[buf][wn * 64 + nt2 * 16 + ((lane >> 4) << 3) + (lane & 7)]
                            [((lane >> 3) & 1) * 8 + kk]);
                LDMATRIX_X4(r4, addr);
                bfr[s][2 * nt2][0] = r4[0];     bfr[s][2 * nt2][1] = r4[1];
                bfr[s][2 * nt2 + 1][0] = r4[2]; bfr[s][2 * nt2 + 1][1] = r4[3];
            }
        }
        #pragma unroll
        for (int s = 0; s < 2; s++)
            #pragma unroll
            for (int mt = 0; mt < 4; mt++)
                #pragma unroll
                for (int nt = 0; nt < 8; nt++)
                    MMA_16816(c[mt][nt], a[s][mt], bfr[s][nt]);
    }

    // Epilogue: +bias, v2 stores
    const int er = lane >> 2;
    const int ec = (lane & 3) * 2;
    #pragma unroll
    for (int mt = 0; mt < 4; mt++) {
        const size_t row0 = (size_t)(m0 + wm * 64 + mt * 16 + er);
        #pragma unroll
        for (int nt = 0; nt < 8; nt++) {
            const int cl = wn * 64 + nt * 8 + ec;
            const float b0 = sbias[cl], b1 = sbias[cl + 1];
            float2 v0 = make_float2(c[mt][nt][0] + b0, c[mt][nt][1] + b1);
            float2 v1 = make_float2(c[mt][nt][2] + b0, c[mt][nt][3] + b1);
            *(float2*)&out[row0 * VOCAB + n0 + cl] = v0;
            *(float2*)&out[(row0 + 8) * VOCAB + n0 + cl] = v1;
        }
    }
}

// ---------------------------------------------------------------------------
// kernel_launch — graph-capturable, allocation-free
// Inputs: X(i32), state, W_ih, W_hh, b_ih, b_hh, W_dense, b_dense
// Output: [8192*8192 fp32 logits][32*256 fp32 final state]
// ---------------------------------------------------------------------------
extern "C" void kernel_launch(void* const* d_in, const int* in_sizes, int n_in,
                              void* d_out, int out_size) {
    const int*   X       = (const int*)  d_in[0];
    const float* state   = (const float*)d_in[1];
    const float* W_ih    = (const float*)d_in[2];
    const float* W_hh    = (const float*)d_in[3];
    const float* b_ih    = (const float*)d_in[4];
    const float* b_hh    = (const float*)d_in[5];
    const float* W_dense = (const float*)d_in[6];
    const float* b_dense = (const float*)d_in[7];
    float* out = (float*)d_out;
    float* out_state = out + (size_t)SEQ * BATCH * VOCAB;

    transpose_wih_kernel<<<dim3(VOCAB / 32, G3H / 32), dim3(32, 8)>>>(W_ih, b_ih);
    convert_wd_kernel<<<(VOCAB * HID + 1023) / 1024, 1024>>>(W_dense);
    gru_kernel<<<BATCH * 4, 384>>>(X, state, W_hh, b_hh, out_state);
    dense_kernel<<<dim3(VOCAB / 128, SEQ * BATCH / 128), 128>>>(b_dense, out);
}